// round 16
// baseline (speedup 1.0000x reference)
#include <cuda_runtime.h>
#include <cuda_bf16.h>

#define RTILE 128            /* samples per block */
#define LANES  64            /* sample-lanes (2 samples per thread) */
#define NSLICE 8             /* atom slices */
#define CAP 1024             /* smem atom list capacity (expected cnt ~138) */

#define TWO_PI_F   6.2831855f   /* float32(2*pi) — matches jnp two_pi */
#define LOG2E_F    1.4426950408889634f

// XLA-GPU lowers f32 divide to div.full.f32 (<=2ulp, NOT correctly rounded).
// This is what makes the t grid match the reference.
__device__ __forceinline__ float div_full(float a, float b) {
    float r;
    asm("div.full.f32 %0, %1, %2;" : "=f"(r) : "f"(a), "f"(b));
    return r;
}
__device__ __forceinline__ float ex2(float x) {
    float r;
    asm("ex2.approx.f32 %0, %1;" : "=f"(r) : "f"(x));
    return r;
}

// ---------------------------------------------------------------------------
// Fused kernel (R15 structure + 3-blocks/SM register cap): vectorized 4-atom
// sweep compaction into SMEM (deterministic atom-index order), then 128
// samples rendered as 64 lanes x 8 slices, 2 samples/thread, interleaved
// LDS.128 list reads. __launch_bounds__(512,3) caps regs at 42 so THREE
// blocks fit per SM (R15 ran 2 at 46 regs -> occ 45%).
// Eval numerics identical (load-bearing non-contracted phase chain).
// ---------------------------------------------------------------------------
__global__ void __launch_bounds__(512, 3) fused_kernel(
    const float* __restrict__ amp,
    const float* __restrict__ tau,
    const float* __restrict__ om,
    const float* __restrict__ sg,
    const float* __restrict__ ph,
    const float* __restrict__ gm,
    float* __restrict__ out, int N, int T)
{
    __shared__ float4 s_p[2 * CAP];         // {tau,om,.5g,phi},{a,nk,4s,0} interleaved
    __shared__ float  s_part[NSLICE][RTILE];
    __shared__ int    s_base;
    __shared__ int    s_warp_cnt[16];

    int tile = blockIdx.x;
    int s0 = tile * RTILE;
    int s1 = min(s0 + RTILE - 1, T - 1);
    float t_lo = (float)s0 / 24000.0f - 1e-4f;   // slack >> 2-ulp grid jitter
    float t_hi = (float)s1 / 24000.0f + 1e-4f;

    if (threadIdx.x == 0) s_base = 0;
    __syncthreads();

    int lane = threadIdx.x & 31;
    int wid  = threadIdx.x >> 5;

    const float4* __restrict__ tau4 = (const float4*)tau;
    const float4* __restrict__ sg4  = (const float4*)sg;

    // ---- Phase 1: ordered compaction, 4 atoms/thread/sweep ----
    for (int base = 0; base < N; base += 2048) {
        int i0 = base + (int)threadIdx.x * 4;   // atoms i0..i0+3 (index order)
        bool act[4] = {false, false, false, false};
        float4 t4 = make_float4(0.f, 0.f, 0.f, 0.f);
        float4 v4 = make_float4(1.f, 1.f, 1.f, 1.f);
        int cnt = 0;
        if (i0 + 3 < N) {
            t4 = tau4[i0 >> 2];
            v4 = sg4[i0 >> 2];
            const float* tp = &t4.x;
            const float* sp = &v4.x;
            #pragma unroll
            for (int k = 0; k < 4; k++) {
                float hw = 4.0f * sp[k];        // exact
                act[k] = (tp[k] - hw <= t_hi) && (tp[k] + hw >= t_lo);
                cnt += act[k] ? 1 : 0;
            }
        }

        // warp inclusive scan of per-thread counts (atom order == thread order)
        int ws = cnt;
        #pragma unroll
        for (int d = 1; d < 32; d <<= 1) {
            int v = __shfl_up_sync(0xFFFFFFFFu, ws, d);
            if (lane >= d) ws += v;
        }
        if (lane == 31) s_warp_cnt[wid] = ws;    // warp total
        __syncthreads();

        int woff = 0, total = 0;
        #pragma unroll
        for (int w = 0; w < 16; w++) {
            int c = s_warp_cnt[w];
            total += c;
            if (w < wid) woff += c;
        }
        int myoff = s_base + woff + (ws - cnt);  // exclusive-in-warp

        if (cnt) {
            const float* tp = &t4.x;
            const float* sp = &v4.x;
            #pragma unroll
            for (int k = 0; k < 4; k++) {
                if (act[k]) {
                    int i = i0 + k;
                    if (myoff < CAP) {
                        float s = sp[k];
                        s_p[2 * myoff]     = make_float4(tp[k], om[i],
                                                         __fmul_rn(0.5f, gm[i]), ph[i]);
                        float denom = __fadd_rn(__fmul_rn(2.0f, __fmul_rn(s, s)), 1e-8f);
                        float nk = -div_full(LOG2E_F, denom);   // ex2-folded env coeff
                        s_p[2 * myoff + 1] = make_float4(amp[i], nk,
                                                         __fmul_rn(4.0f, s), 0.0f);
                    }
                    myoff++;
                }
            }
        }
        __syncthreads();
        if (threadIdx.x == 0) s_base += total;
        __syncthreads();
    }
    int cnt = min(s_base, CAP);

    // ---- Phase 2: render 2 samples/thread from the SMEM list ----
    int x     = threadIdx.x & (LANES - 1);
    int slice = threadIdx.x >> 6;
    int sA    = s0 + x;
    int sB    = sA + LANES;
    float tA  = div_full((float)sA, 24000.0f);   // reference-matching t grid
    float tB  = div_full((float)sB, 24000.0f);

    float accA = 0.0f, accB = 0.0f;
    const float4* p = s_p + 2 * slice;
    #pragma unroll 2
    for (int j = slice; j < cnt; j += NSLICE, p += 2 * NSLICE) {
        float4 A = p[0];   // tau, omega, 0.5*gamma, phi   (LDS.128 broadcast)
        float4 B = p[1];   // a, -log2e/denom, 4sigma, -

        // ---- sample A ----
        {
            float tc  = __fadd_rn(tA, -A.x);
            float tc2 = __fmul_rn(tc, tc);
            float env = ex2(tc2 * B.y);
            float r1  = __fmul_rn(A.y, tc);
            float r3  = __fmul_rn(A.z, tc);
            float r4  = __fmul_rn(r3, tc);
            float sm  = __fadd_rn(r1, r4);
            float p2  = __fmul_rn(TWO_PI_F, sm);
            float phase = __fadd_rn(p2, A.w);
            float c   = __cosf(phase);
            float v   = __fmul_rn(__fmul_rn(B.x, env), c);
            if (fabsf(tc) <= B.z) accA = __fadd_rn(accA, v);
        }
        // ---- sample B ----
        {
            float tc  = __fadd_rn(tB, -A.x);
            float tc2 = __fmul_rn(tc, tc);
            float env = ex2(tc2 * B.y);
            float r1  = __fmul_rn(A.y, tc);
            float r3  = __fmul_rn(A.z, tc);
            float r4  = __fmul_rn(r3, tc);
            float sm  = __fadd_rn(r1, r4);
            float p2  = __fmul_rn(TWO_PI_F, sm);
            float phase = __fadd_rn(p2, A.w);
            float c   = __cosf(phase);
            float v   = __fmul_rn(__fmul_rn(B.x, env), c);
            if (fabsf(tc) <= B.z) accB = __fadd_rn(accB, v);
        }
    }

    s_part[slice][x]         = accA;
    s_part[slice][x + LANES] = accB;
    __syncthreads();

    // threads 0..127 reduce one sample column over 8 slices, fixed order
    if (threadIdx.x < RTILE) {
        int xs = threadIdx.x;
        int s  = s0 + xs;
        if (s < T) {
            float r = s_part[0][xs];
            #pragma unroll
            for (int k = 1; k < NSLICE; k++) r = __fadd_rn(r, s_part[k][xs]);
            out[s] = r;
        }
    }
}

extern "C" void kernel_launch(void* const* d_in, const int* in_sizes, int n_in,
                              void* d_out, int out_size)
{
    const float* amp = (const float*)d_in[0];
    const float* tau = (const float*)d_in[1];
    const float* om  = (const float*)d_in[2];
    const float* sg  = (const float*)d_in[3];
    const float* ph  = (const float*)d_in[4];
    const float* gm  = (const float*)d_in[5];
    // d_in[6] = num_samples scalar — T comes from out_size.

    int N = in_sizes[0];
    int T = out_size;
    int num_tiles = (T + RTILE - 1) / RTILE;      // 72000 -> 563

    fused_kernel<<<num_tiles, 512>>>(amp, tau, om, sg, ph, gm, (float*)d_out, N, T);
}